// round 6
// baseline (speedup 1.0000x reference)
#include <cuda_runtime.h>
#include <cuda_fp16.h>

// fp16 pyramid, levels 0..7. Texels/plane: 512^2 + 256^2 + ... + 4^2 = 349520.
#define T_ALL 349520
__device__ __half g_pyrh[3 * T_ALL * 16];     // 33.6 MB
__device__ float4 g_l4[3 * 1024 * 4];         // fp32 level 4 (32x32/plane), c4-sliced
__device__ unsigned g_ctr = 0;

// texel offset of level l (0..7) within a plane's fp16 region
__constant__ int c_off[8] = {0, 262144, 327680, 344064, 348160, 349184, 349440, 349504};

__device__ __forceinline__ void st_h4(__half* p, float4 v) {
    __half2 a = __floats2half2_rn(v.x, v.y);
    __half2 b = __floats2half2_rn(v.z, v.w);
    uint2 u;
    u.x = *reinterpret_cast<unsigned*>(&a);
    u.y = *reinterpret_cast<unsigned*>(&b);
    *reinterpret_cast<uint2*>(p) = u;
}

__device__ __forceinline__ float4 avg4(float4 a, float4 b, float4 c, float4 d) {
    float4 r;
    r.x = (a.x + b.x + c.x + d.x) * 0.25f;
    r.y = (a.y + b.y + c.y + d.y) * 0.25f;
    r.z = (a.z + b.z + c.z + d.z) * 0.25f;
    r.w = (a.w + b.w + c.w + d.w) * 0.25f;
    return r;
}

// ---------------------------------------------------------------------------
// ds_fused: block = (plane, 16x16 L0 tile). Coalesced fm load into smem,
// fp16 L0 copy (coalesced), cascade L1..L4 in smem. Last block builds L5..L7.
// grid = 3 * 1024 blocks, 256 threads.
// ---------------------------------------------------------------------------
__global__ void __launch_bounds__(256) ds_fused(const float4* __restrict__ fm) {
    __shared__ float4 s0[1024];   // 16x16 texels x 4 f4 (16KB)
    __shared__ float4 s1[256];    // 8x8
    __shared__ float4 s2[64];     // 4x4
    __shared__ float4 s3[16];     // 2x2
    __shared__ bool   isLast;

    const int b = blockIdx.x;
    const int tile = b & 1023;
    const int plane = b >> 10;
    const int tx = tile & 31, ty = tile >> 5;
    const int tid = threadIdx.x;

    const float4* src = fm + (size_t)plane * (512 * 512 * 4);
    __half* hp = g_pyrh + (size_t)plane * T_ALL * 16;

    // Load 16x16x4 = 1024 float4, 4 per thread; write fp16 L0 coalesced.
    #pragma unroll
    for (int i = 0; i < 4; ++i) {
        int idx = i * 256 + tid;
        int r = idx >> 6, o = idx & 63;          // o = texel_in_row*4 + c4
        float4 v = __ldg(src + (size_t)(ty * 16 + r) * 2048 + tx * 64 + o);
        s0[idx] = v;
        const size_t gtex = (size_t)(ty * 16 + r) * 512 + tx * 16 + (o >> 2);
        st_h4(hp + gtex * 16 + (o & 3) * 4, v);
    }
    __syncthreads();

    // L1: 8x8 texels x4
    {
        int c4 = tid & 3, x = (tid >> 2) & 7, y = tid >> 5;
        float4 v = avg4(s0[((2 * y) * 16 + 2 * x) * 4 + c4],
                        s0[((2 * y) * 16 + 2 * x + 1) * 4 + c4],
                        s0[((2 * y + 1) * 16 + 2 * x) * 4 + c4],
                        s0[((2 * y + 1) * 16 + 2 * x + 1) * 4 + c4]);
        s1[tid] = v;
        st_h4(hp + (size_t)(c_off[1] + (ty * 8 + y) * 256 + tx * 8 + x) * 16 + c4 * 4, v);
    }
    __syncthreads();

    // L2: 4x4 x4
    if (tid < 64) {
        int c4 = tid & 3, x = (tid >> 2) & 3, y = tid >> 4;
        float4 v = avg4(s1[((2 * y) * 8 + 2 * x) * 4 + c4],
                        s1[((2 * y) * 8 + 2 * x + 1) * 4 + c4],
                        s1[((2 * y + 1) * 8 + 2 * x) * 4 + c4],
                        s1[((2 * y + 1) * 8 + 2 * x + 1) * 4 + c4]);
        s2[tid] = v;
        st_h4(hp + (size_t)(c_off[2] + (ty * 4 + y) * 128 + tx * 4 + x) * 16 + c4 * 4, v);
    }
    __syncthreads();

    // L3: 2x2 x4
    if (tid < 16) {
        int c4 = tid & 3, x = (tid >> 2) & 1, y = tid >> 3;
        float4 v = avg4(s2[((2 * y) * 4 + 2 * x) * 4 + c4],
                        s2[((2 * y) * 4 + 2 * x + 1) * 4 + c4],
                        s2[((2 * y + 1) * 4 + 2 * x) * 4 + c4],
                        s2[((2 * y + 1) * 4 + 2 * x + 1) * 4 + c4]);
        s3[tid] = v;
        st_h4(hp + (size_t)(c_off[3] + (ty * 2 + y) * 64 + tx * 2 + x) * 16 + c4 * 4, v);
    }
    __syncthreads();

    // L4: one texel per tile
    if (tid < 4) {
        int c4 = tid;
        float4 v = avg4(s3[0 * 4 + c4], s3[1 * 4 + c4], s3[2 * 4 + c4], s3[3 * 4 + c4]);
        st_h4(hp + (size_t)(c_off[4] + ty * 32 + tx) * 16 + c4 * 4, v);
        g_l4[((size_t)plane * 1024 + ty * 32 + tx) * 4 + c4] = v;
    }

    // ---- last block builds L5..L7 from fp32 L4 ----
    if (tid == 0) {
        __threadfence();
        unsigned c = atomicAdd(&g_ctr, 1u);
        isLast = (c == (unsigned)(gridDim.x - 1));
    }
    __syncthreads();
    if (!isLast) return;
    if (tid == 0) g_ctr = 0;       // reset for next graph replay
    __threadfence();               // see all blocks' g_l4 writes

    for (int pl = 0; pl < 3; ++pl) {
        __half* hq = g_pyrh + (size_t)pl * T_ALL * 16;
        const float4* L4 = g_l4 + (size_t)pl * 1024 * 4;
        __syncthreads();
        // L5: 16x16 x4 = 1024 items
        for (int k = tid; k < 1024; k += 256) {
            int c4 = k & 3, x = (k >> 2) & 15, y = k >> 6;
            float4 v = avg4(L4[((2 * y) * 32 + 2 * x) * 4 + c4],
                            L4[((2 * y) * 32 + 2 * x + 1) * 4 + c4],
                            L4[((2 * y + 1) * 32 + 2 * x) * 4 + c4],
                            L4[((2 * y + 1) * 32 + 2 * x + 1) * 4 + c4]);
            s0[k] = v;
            st_h4(hq + (size_t)(c_off[5] + y * 16 + x) * 16 + c4 * 4, v);
        }
        __syncthreads();
        // L6: 8x8 x4 = 256 items
        {
            int c4 = tid & 3, x = (tid >> 2) & 7, y = tid >> 5;
            float4 v = avg4(s0[((2 * y) * 16 + 2 * x) * 4 + c4],
                            s0[((2 * y) * 16 + 2 * x + 1) * 4 + c4],
                            s0[((2 * y + 1) * 16 + 2 * x) * 4 + c4],
                            s0[((2 * y + 1) * 16 + 2 * x + 1) * 4 + c4]);
            st_h4(hq + (size_t)(c_off[6] + y * 8 + x) * 16 + c4 * 4, v);
        }
        // L7: 4x4 x4 via 4x4 box of L5
        if (tid < 64) {
            int c4 = tid & 3, x = (tid >> 2) & 3, y = tid >> 4;
            float4 acc = make_float4(0.f, 0.f, 0.f, 0.f);
            #pragma unroll
            for (int dy = 0; dy < 4; ++dy)
                #pragma unroll
                for (int dx = 0; dx < 4; ++dx) {
                    float4 t = s0[((4 * y + dy) * 16 + 4 * x + dx) * 4 + c4];
                    acc.x += t.x; acc.y += t.y; acc.z += t.z; acc.w += t.w;
                }
            float4 v = make_float4(acc.x * 0.0625f, acc.y * 0.0625f,
                                   acc.z * 0.0625f, acc.w * 0.0625f);
            st_h4(hq + (size_t)(c_off[7] + y * 4 + x) * 16 + c4 * 4, v);
        }
    }
}

// ---------------------------------------------------------------------------
// Sample: 4 lanes per (point, plane): lane = (cx, c2). Branchless, uniform
// fp16 path for both mip taps; all 4 LDGs issued before any math consumes them.
// ---------------------------------------------------------------------------
__global__ void __launch_bounds__(256) sample_kernel(
        const float* __restrict__ xin,
        const float* __restrict__ level,
        float4* __restrict__ out, int N3) {
    const int gid = blockIdx.x * blockDim.x + threadIdx.x;
    const int ps = gid >> 2;
    if (ps >= N3) return;
    const int sub = gid & 3;
    const int c2 = sub & 1;
    const int cx = sub >> 1;
    const int pt = ps / 3;
    const int plane = ps - pt * 3;

    const float xv = __ldg(xin + pt * 3 + 0);
    const float yv = __ldg(xin + pt * 3 + 1);
    const float zv = __ldg(xin + pt * 3 + 2);
    const float u = (plane == 0) ? yv : xv;
    const float v = (plane == 2) ? yv : zv;

    float lvl = fminf(fmaxf(__ldg(level + pt), 0.f), 7.f);
    const float l0f = floorf(lvl);
    const float f = lvl - l0f;
    const int l0 = (int)l0f;
    const int l1 = min(l0 + 1, 7);

    const uint4* pyr = reinterpret_cast<const uint4*>(g_pyrh) + (size_t)plane * T_ALL * 2;

    // ---- tap 0 addresses ----
    const int sz0 = 512 >> l0;
    const float px0 = u * (float)sz0 - 0.5f;
    const float py0 = v * (float)sz0 - 0.5f;
    const float x0f0 = floorf(px0), y0f0 = floorf(py0);
    const float fx0 = px0 - x0f0, fy0 = py0 - y0f0;
    const int sm0 = sz0 - 1;
    const int xa0 = min(max((int)x0f0, 0), sm0);
    const int xb0 = min(max((int)x0f0 + 1, 0), sm0);
    const int ya0 = min(max((int)y0f0, 0), sm0);
    const int yb0 = min(max((int)y0f0 + 1, 0), sm0);
    const int xc0 = cx ? xb0 : xa0;
    const uint4* b0 = pyr + c_off[l0] * 2;

    // ---- tap 1 addresses ----
    const int sz1 = 512 >> l1;
    const float px1 = u * (float)sz1 - 0.5f;
    const float py1 = v * (float)sz1 - 0.5f;
    const float x0f1 = floorf(px1), y0f1 = floorf(py1);
    const float fx1 = px1 - x0f1, fy1 = py1 - y0f1;
    const int sm1 = sz1 - 1;
    const int xa1 = min(max((int)x0f1, 0), sm1);
    const int xb1 = min(max((int)x0f1 + 1, 0), sm1);
    const int ya1 = min(max((int)y0f1, 0), sm1);
    const int yb1 = min(max((int)y0f1 + 1, 0), sm1);
    const int xc1 = cx ? xb1 : xa1;
    const uint4* b1 = pyr + c_off[l1] * 2;

    // ---- 4 independent loads, front-batched ----
    const uint4 ra0 = __ldg(b0 + (ya0 * sz0 + xc0) * 2 + c2);
    const uint4 rb0 = __ldg(b0 + (yb0 * sz0 + xc0) * 2 + c2);
    const uint4 ra1 = __ldg(b1 + (ya1 * sz1 + xc1) * 2 + c2);
    const uint4 rb1 = __ldg(b1 + (yb1 * sz1 + xc1) * 2 + c2);

    float4 A = make_float4(0.f, 0.f, 0.f, 0.f);
    float4 B = make_float4(0.f, 0.f, 0.f, 0.f);

    // tap 0 combine
    {
        const __half2 wya = __float2half2_rn(1.f - fy0);
        const __half2 wyb = __float2half2_rn(fy0);
        const __half2 h0 = __hfma2(*(const __half2*)&rb0.x, wyb, __hmul2(*(const __half2*)&ra0.x, wya));
        const __half2 h1 = __hfma2(*(const __half2*)&rb0.y, wyb, __hmul2(*(const __half2*)&ra0.y, wya));
        const __half2 h2 = __hfma2(*(const __half2*)&rb0.z, wyb, __hmul2(*(const __half2*)&ra0.z, wya));
        const __half2 h3 = __hfma2(*(const __half2*)&rb0.w, wyb, __hmul2(*(const __half2*)&ra0.w, wya));
        const float wl = (cx ? fx0 : (1.f - fx0)) * (1.f - f);
        const float2 f0 = __half22float2(h0);
        const float2 f1 = __half22float2(h1);
        const float2 f2 = __half22float2(h2);
        const float2 f3 = __half22float2(h3);
        A.x = fmaf(wl, f0.x, A.x); A.y = fmaf(wl, f0.y, A.y);
        A.z = fmaf(wl, f1.x, A.z); A.w = fmaf(wl, f1.y, A.w);
        B.x = fmaf(wl, f2.x, B.x); B.y = fmaf(wl, f2.y, B.y);
        B.z = fmaf(wl, f3.x, B.z); B.w = fmaf(wl, f3.y, B.w);
    }
    // tap 1 combine
    {
        const __half2 wya = __float2half2_rn(1.f - fy1);
        const __half2 wyb = __float2half2_rn(fy1);
        const __half2 h0 = __hfma2(*(const __half2*)&rb1.x, wyb, __hmul2(*(const __half2*)&ra1.x, wya));
        const __half2 h1 = __hfma2(*(const __half2*)&rb1.y, wyb, __hmul2(*(const __half2*)&ra1.y, wya));
        const __half2 h2 = __hfma2(*(const __half2*)&rb1.z, wyb, __hmul2(*(const __half2*)&ra1.z, wya));
        const __half2 h3 = __hfma2(*(const __half2*)&rb1.w, wyb, __hmul2(*(const __half2*)&ra1.w, wya));
        const float wl = (cx ? fx1 : (1.f - fx1)) * f;
        const float2 f0 = __half22float2(h0);
        const float2 f1 = __half22float2(h1);
        const float2 f2 = __half22float2(h2);
        const float2 f3 = __half22float2(h3);
        A.x = fmaf(wl, f0.x, A.x); A.y = fmaf(wl, f0.y, A.y);
        A.z = fmaf(wl, f1.x, A.z); A.w = fmaf(wl, f1.y, A.w);
        B.x = fmaf(wl, f2.x, B.x); B.y = fmaf(wl, f2.y, B.y);
        B.z = fmaf(wl, f3.x, B.z); B.w = fmaf(wl, f3.y, B.w);
    }

    // reduce over cx (xor lane mask 2)
    const unsigned m = 0xFFFFFFFFu;
    A.x += __shfl_xor_sync(m, A.x, 2);
    A.y += __shfl_xor_sync(m, A.y, 2);
    A.z += __shfl_xor_sync(m, A.z, 2);
    A.w += __shfl_xor_sync(m, A.w, 2);
    B.x += __shfl_xor_sync(m, B.x, 2);
    B.y += __shfl_xor_sync(m, B.y, 2);
    B.z += __shfl_xor_sync(m, B.z, 2);
    B.w += __shfl_xor_sync(m, B.w, 2);

    const float4 o = cx ? B : A;
    out[ps * 4 + c2 * 2 + cx] = o;
}

extern "C" void kernel_launch(void* const* d_in, const int* in_sizes, int n_in,
                              void* d_out, int out_size) {
    const float*  x     = (const float*)d_in[0];
    const float*  level = (const float*)d_in[1];
    const float4* fm    = (const float4*)d_in[2];
    float4* out = (float4*)d_out;
    const int N = in_sizes[0] / 3;
    const int N3 = N * 3;

    ds_fused<<<3 * 1024, 256>>>(fm);

    const int total = N3 * 4;
    const int threads = 256;
    sample_kernel<<<(total + threads - 1) / threads, threads>>>(x, level, out, N3);
}